// round 10
// baseline (speedup 1.0000x reference)
#include <cuda_runtime.h>
#include <math.h>

#define BB    4
#define SSEQ  4096
#define IND   1024
#define OUTD  1024
#define EE    8
#define LSCALE 512.0f

// ---- scratch (device globals; allocation is forbidden) ----
__device__ float    g_seg[BB * IND];               // 16 KB : per-batch column sums
__device__ float    g_h[(size_t)BB * SSEQ * EE];   // 512 KB: all-expert dots
__device__ float    g_coef[BB * 2];
__device__ int      g_idx[BB * 2];
__device__ unsigned g_arrive;                      // k1 completion counter

typedef unsigned long long u64;

__device__ __forceinline__ void fma2(u64& d, u64 a, u64 b) {
    asm("fma.rn.f32x2 %0, %1, %2, %0;" : "+l"(d) : "l"(a), "l"(b));
}
__device__ __forceinline__ void add2(u64& d, u64 a) {
    asm("add.rn.f32x2 %0, %0, %1;" : "+l"(d) : "l"(a));
}
__device__ __forceinline__ float lo2(u64 v) { return __uint_as_float((unsigned)(v & 0xffffffffull)); }
__device__ __forceinline__ float hi2(u64 v) { return __uint_as_float((unsigned)(v >> 32)); }

// streaming 16B store (out is never re-read)
__device__ __forceinline__ void stcs4(float* p, float4 v) {
    asm volatile("st.global.cs.v4.f32 [%0], {%1, %2, %3, %4};"
                 :: "l"(p), "f"(v.x), "f"(v.y), "f"(v.z), "f"(v.w));
}

// ------------------------------------------------------------------
// K1: round-2 hot loop (measured 22.9us) + fused gating tail using a
// single acq_rel arrive atomic (NO __threadfence / L1 flush).
// grid = 512 blocks (32 tokens each), 256 threads, 2 CTAs/SM.
// ------------------------------------------------------------------
#define TPW  4      // tokens per warp
#define TOKB 32     // tokens per block

extern __shared__ float s_dyn[];

__global__ void __launch_bounds__(256, 2) k1_dots(const float* __restrict__ x,
                                                  const float* __restrict__ lora_A,
                                                  const float* __restrict__ gate_w,
                                                  const float* __restrict__ gate_b) {
    float* A_s  = s_dyn;          // 8192 floats (32 KB), [e][1024]
    float* segp = s_dyn + 8192;   // 8192 floats (32 KB), [warp][1024]

    const int tid  = threadIdx.x;
    const int w    = tid >> 5;
    const int lane = tid & 31;
    const int b       = blockIdx.x >> 7;           // 128 blocks per batch
    const int tokbase = (blockIdx.x & 127) * TOKB;

    // stage A once (contiguous copy, conflict-free)
    #pragma unroll
    for (int j = 0; j < 8; ++j) {
        int i4 = tid + j * 256;                    // 2048 float4 total
        ((float4*)A_s)[i4] = ((const float4*)lora_A)[i4];
    }
    __syncthreads();

    u64 acc[TPW][EE];
    #pragma unroll
    for (int i = 0; i < TPW; ++i)
        #pragma unroll
        for (int e = 0; e < EE; ++e) acc[i][e] = 0ull;

    const float* xw = x + ((size_t)(b * SSEQ + tokbase + w * TPW)) * IND;

    #pragma unroll
    for (int c = 0; c < 8; ++c) {                  // 8 k-chunks of 128
        const int koff = c * 128 + lane * 4;

        // x for this warp's 4 tokens (coalesced LDG.128)
        u64 xlo[TPW], xhi[TPW];
        u64 seglo = 0ull, seghi = 0ull;
        #pragma unroll
        for (int i = 0; i < TPW; ++i) {
            double2 xv = *(const double2*)(xw + (size_t)i * IND + koff);
            xlo[i] = __double_as_longlong(xv.x);
            xhi[i] = __double_as_longlong(xv.y);
            add2(seglo, xlo[i]);
            add2(seghi, xhi[i]);
        }

        // 8 experts, A float4 from shared (conflict-free, 2 live regs)
        #pragma unroll
        for (int e = 0; e < EE; ++e) {
            double2 av = *(const double2*)&A_s[e * IND + koff];
            u64 alo = __double_as_longlong(av.x);
            u64 ahi = __double_as_longlong(av.y);
            #pragma unroll
            for (int i = 0; i < TPW; ++i) {
                fma2(acc[i][e], xlo[i], alo);
                fma2(acc[i][e], xhi[i], ahi);
            }
        }

        // flush this chunk's seg partial (each slot written exactly once)
        double2 sv;
        sv.x = __longlong_as_double(seglo);
        sv.y = __longlong_as_double(seghi);
        *(double2*)&segp[w * IND + koff] = sv;
    }

    // ---- per-token cross-lane reduction (butterfly) + h store ----
    #pragma unroll
    for (int i = 0; i < TPW; ++i) {
        float v[EE];
        #pragma unroll
        for (int e = 0; e < EE; ++e) v[e] = lo2(acc[i][e]) + hi2(acc[i][e]);
        #pragma unroll
        for (int off = 16; off; off >>= 1)
            #pragma unroll
            for (int e = 0; e < EE; ++e)
                v[e] += __shfl_xor_sync(0xffffffffu, v[e], off);
        if (lane == 0) {
            size_t gt = (size_t)b * SSEQ + tokbase + w * TPW + i;
            *(float4*)&g_h[gt * EE]     = make_float4(v[0], v[1], v[2], v[3]);
            *(float4*)&g_h[gt * EE + 4] = make_float4(v[4], v[5], v[6], v[7]);
        }
    }

    // ---- cross-warp seg reduction + REDG ----
    __syncthreads();
    {
        float4 s = ((float4*)segp)[tid];           // warp 0's row
        #pragma unroll
        for (int ww = 1; ww < 8; ++ww) {
            float4 t = *(float4*)&segp[ww * IND + tid * 4];
            s.x += t.x; s.y += t.y; s.z += t.z; s.w += t.w;
        }
        float* dst = &g_seg[b * IND + tid * 4];
        atomicAdd(dst + 0, s.x);
        atomicAdd(dst + 1, s.y);
        atomicAdd(dst + 2, s.z);
        atomicAdd(dst + 3, s.w);
    }

    // ====== fused gating: last CTA (acq_rel arrive, no threadfence) ======
    __shared__ unsigned s_last;
    __syncthreads();                               // all 4 REDGs issued
    if (tid == 0) {
        unsigned old;
        asm volatile("atom.acq_rel.gpu.global.add.u32 %0, [%1], 1;"
                     : "=r"(old) : "l"(&g_arrive) : "memory");
        s_last = (old == (unsigned)(gridDim.x - 1)) ? 1u : 0u;
    }
    __syncthreads();
    if (!s_last) return;

    __shared__ float dots[BB * EE];
    {
        int pair = tid >> 3, l8 = tid & 7;         // 32 (b,e) pairs x 8 threads
        int bb = pair >> 3, e = pair & 7;
        float s = 0.f;
        #pragma unroll 8
        for (int k = l8 * 4; k < IND; k += 32) {
            float4 a = *(const float4*)&g_seg[bb * IND + k];
            float4 g = *(const float4*)&gate_w[e * IND + k];
            s += a.x * g.x + a.y * g.y + a.z * g.z + a.w * g.w;
        }
        #pragma unroll
        for (int o = 4; o; o >>= 1) s += __shfl_xor_sync(0xffffffffu, s, o);
        if (l8 == 0) dots[pair] = s * (1.0f / (float)SSEQ) + gate_b[e];
    }
    __syncthreads();

    // zero g_seg for next replay (1024 float4, 4 per thread)
    #pragma unroll
    for (int j = 0; j < 4; ++j)
        ((float4*)g_seg)[tid + j * 256] = make_float4(0.f, 0.f, 0.f, 0.f);

    if (tid < BB) {
        int bb = tid;
        float l[EE]; float mx = -1e30f;
        #pragma unroll
        for (int i = 0; i < EE; ++i) { l[i] = dots[bb * EE + i]; mx = fmaxf(mx, l[i]); }
        float sum = 0.f;
        #pragma unroll
        for (int i = 0; i < EE; ++i) { l[i] = expf(l[i] - mx); sum += l[i]; }
        int i0 = 0;
        #pragma unroll
        for (int i = 1; i < EE; ++i) if (l[i] > l[i0]) i0 = i;     // ties -> lowest idx
        int i1 = (i0 == 0) ? 1 : 0;
        #pragma unroll
        for (int i = 0; i < EE; ++i) if (i != i0 && l[i] > l[i1]) i1 = i;
        g_idx[bb * 2] = i0;  g_idx[bb * 2 + 1] = i1;
        float f = LSCALE / sum;
        g_coef[bb * 2]     = l[i0] * f;
        g_coef[bb * 2 + 1] = l[i1] * f;
    }
    if (tid == 0) g_arrive = 0;                    // reset for next graph replay
}

// ------------------------------------------------------------------
// K3: out = c0*B_{e0} + c1*B_{e1}. TC=32/block, grid 512. All 32
// coef pairs loaded to registers BEFORE the store loop -> store loop
// is pure FFMA->STG.128, fully independent, no LDS in the chain.
// ------------------------------------------------------------------
#define TC 32
__global__ void __launch_bounds__(256) k3_out(const float* __restrict__ lora_B,
                                              float* __restrict__ out) {
    __shared__ float2 cs[TC];
    const int tid = threadIdx.x;
    const int b = blockIdx.x >> 7;                 // 128 blocks per batch
    const int tokbase = (blockIdx.x & 127) * TC;
    const int e0 = g_idx[b * 2], e1 = g_idx[b * 2 + 1];
    const float w0 = g_coef[b * 2], w1 = g_coef[b * 2 + 1];

    if (tid < TC) {
        size_t gt = (size_t)b * SSEQ + tokbase + tid;
        cs[tid] = make_float2(w0 * g_h[gt * EE + e0], w1 * g_h[gt * EE + e1]);
    }
    float4 B0 = *(const float4*)&lora_B[e0 * OUTD + tid * 4];
    float4 B1 = *(const float4*)&lora_B[e1 * OUTD + tid * 4];
    __syncthreads();

    // hoist ALL coef pairs into registers (16 x u64 = 16 regs)
    float2 cr[TC];
    #pragma unroll
    for (int i = 0; i < TC; ++i) cr[i] = cs[i];

    float* ob = out + ((size_t)b * SSEQ + tokbase) * OUTD + tid * 4;
    #pragma unroll 8
    for (int i = 0; i < TC; ++i) {
        float4 v;
        v.x = cr[i].x * B0.x + cr[i].y * B1.x;
        v.y = cr[i].x * B0.y + cr[i].y * B1.y;
        v.z = cr[i].x * B0.z + cr[i].y * B1.z;
        v.w = cr[i].x * B0.w + cr[i].y * B1.w;
        stcs4(ob + (size_t)i * OUTD, v);
    }
}

// ------------------------------------------------------------------
extern "C" void kernel_launch(void* const* d_in, const int* in_sizes, int n_in,
                              void* d_out, int out_size) {
    const float* x      = (const float*)d_in[0];
    const float* lora_A = (const float*)d_in[1];
    const float* lora_B = (const float*)d_in[2];
    const float* gate_w = (const float*)d_in[3];
    const float* gate_b = (const float*)d_in[4];
    float* out = (float*)d_out;

    static bool attr_set = false;
    if (!attr_set) {
        cudaFuncSetAttribute(k1_dots, cudaFuncAttributeMaxDynamicSharedMemorySize, 65536);
        attr_set = true;
    }

    k1_dots<<<BB * (SSEQ / TOKB), 256, 65536>>>(x, lora_A, gate_w, gate_b);
    k3_out<<<BB * (SSEQ / TC), 256>>>(lora_B, out);
}

// round 11
// speedup vs baseline: 1.1941x; 1.1941x over previous
#include <cuda_runtime.h>
#include <math.h>

#define BB    4
#define SSEQ  4096
#define IND   1024
#define OUTD  1024
#define EE    8
#define LSCALE 512.0f

// ---- scratch (device globals; allocation is forbidden) ----
__device__ float    g_seg[BB * IND];   // 16 KB : per-batch column sums (zeroed after use)
__device__ float    g_coef[BB * 2];
__device__ int      g_idx[BB * 2];
__device__ unsigned g_arrive;          // P1 completion counter (reset in tail)

typedef unsigned long long u64;

__device__ __forceinline__ void fma2(u64& d, u64 a, u64 b) {
    asm("fma.rn.f32x2 %0, %1, %2, %0;" : "+l"(d) : "l"(a), "l"(b));
}
__device__ __forceinline__ float lo2(u64 v) { return __uint_as_float((unsigned)(v & 0xffffffffull)); }
__device__ __forceinline__ float hi2(u64 v) { return __uint_as_float((unsigned)(v >> 32)); }

// streaming 16B store (out is never re-read)
__device__ __forceinline__ void stcs4(float* p, float4 v) {
    asm volatile("st.global.cs.v4.f32 [%0], {%1, %2, %3, %4};"
                 :: "l"(p), "f"(v.x), "f"(v.y), "f"(v.z), "f"(v.w));
}

// ------------------------------------------------------------------
// P1: seg[b][col] = sum_s x[b,s,col]  (pure streaming read; x stays
// resident in L2 for P2). grid=512 (32 rows each), 256 thr.
// Thread owns 4 columns; unroll-8 row loop -> 8 LDG.128 in flight.
// Fused gating tail in the last CTA (acq_rel arrive; no L1 flush).
// ------------------------------------------------------------------
__global__ void __launch_bounds__(256) p1_seg(const float* __restrict__ x,
                                              const float* __restrict__ gate_w,
                                              const float* __restrict__ gate_b) {
    const int tid = threadIdx.x;
    const int b       = blockIdx.x >> 7;            // 128 blocks per batch
    const int rowbase = (blockIdx.x & 127) * 32;

    const float* xp = x + ((size_t)b * SSEQ + rowbase) * IND + tid * 4;
    float4 acc = make_float4(0.f, 0.f, 0.f, 0.f);
    #pragma unroll 8
    for (int r = 0; r < 32; ++r) {
        float4 v = *(const float4*)(xp + (size_t)r * IND);
        acc.x += v.x; acc.y += v.y; acc.z += v.z; acc.w += v.w;
    }
    {
        float* dst = &g_seg[b * IND + tid * 4];
        atomicAdd(dst + 0, acc.x);
        atomicAdd(dst + 1, acc.y);
        atomicAdd(dst + 2, acc.z);
        atomicAdd(dst + 3, acc.w);
    }

    // ====== fused gating: last CTA (acq_rel arrive; proven R9) ======
    __shared__ unsigned s_last;
    __syncthreads();
    if (tid == 0) {
        unsigned old;
        asm volatile("atom.acq_rel.gpu.global.add.u32 %0, [%1], 1;"
                     : "=r"(old) : "l"(&g_arrive) : "memory");
        s_last = (old == (unsigned)(gridDim.x - 1)) ? 1u : 0u;
    }
    __syncthreads();
    if (!s_last) return;

    __shared__ float dots[BB * EE];
    {
        int pair = tid >> 3, l8 = tid & 7;          // 32 (b,e) pairs x 8 threads
        int bb = pair >> 3, e = pair & 7;
        float s = 0.f;
        #pragma unroll 8
        for (int k = l8 * 4; k < IND; k += 32) {
            float4 a = *(const float4*)&g_seg[bb * IND + k];
            float4 g = *(const float4*)&gate_w[e * IND + k];
            s += a.x * g.x + a.y * g.y + a.z * g.z + a.w * g.w;
        }
        #pragma unroll
        for (int o = 4; o; o >>= 1) s += __shfl_xor_sync(0xffffffffu, s, o);
        if (l8 == 0) dots[pair] = s * (1.0f / (float)SSEQ) + gate_b[e];
    }
    __syncthreads();

    // zero g_seg for the next graph replay (1024 float4, 4/thread)
    #pragma unroll
    for (int j = 0; j < 4; ++j)
        ((float4*)g_seg)[tid + j * 256] = make_float4(0.f, 0.f, 0.f, 0.f);

    if (tid < BB) {
        int bb = tid;
        float l[EE]; float mx = -1e30f;
        #pragma unroll
        for (int i = 0; i < EE; ++i) { l[i] = dots[bb * EE + i]; mx = fmaxf(mx, l[i]); }
        float sum = 0.f;
        #pragma unroll
        for (int i = 0; i < EE; ++i) { l[i] = expf(l[i] - mx); sum += l[i]; }
        int i0 = 0;
        #pragma unroll
        for (int i = 1; i < EE; ++i) if (l[i] > l[i0]) i0 = i;     // ties -> lowest idx
        int i1 = (i0 == 0) ? 1 : 0;
        #pragma unroll
        for (int i = 0; i < EE; ++i) if (i != i0 && l[i] > l[i1]) i1 = i;
        g_idx[bb * 2] = i0;  g_idx[bb * 2 + 1] = i1;
        float f = LSCALE / sum;
        g_coef[bb * 2]     = l[i0] * f;
        g_coef[bb * 2 + 1] = l[i1] * f;
    }
    if (tid == 0) g_arrive = 0;                     // reset for next replay
}

// ------------------------------------------------------------------
// P2: fused select + project. Per 32-token tile:
//   phase A: warp computes h_e0, h_e1 for its 4 tokens (x from L2,
//            A_e0/A_e1 staged in 8KB smem, k-paired f32x2 FMAs),
//            butterfly-reduce, lane0 writes (w0*h0, w1*h1) to cs[].
//   phase B: R9-k3's proven store loop (B register-resident,
//            cs[] via LDS broadcast, streaming STG.128).
// grid = 512 (128/batch), 256 thr, 3 CTAs/SM target.
// ------------------------------------------------------------------
#define TOKB 32
#define TPW  4

__global__ void __launch_bounds__(256, 3) p2_out(const float* __restrict__ x,
                                                 const float* __restrict__ lora_A,
                                                 const float* __restrict__ lora_B,
                                                 float* __restrict__ out) {
    __shared__ float  A2[2 * IND];     // 8 KB : selected experts' A rows
    __shared__ float2 cs[TOKB];

    const int tid  = threadIdx.x;
    const int w    = tid >> 5;
    const int lane = tid & 31;
    const int b       = blockIdx.x >> 7;            // 128 blocks per batch
    const int tokbase = (blockIdx.x & 127) * TOKB;

    const int e0 = g_idx[b * 2], e1 = g_idx[b * 2 + 1];
    const float w0 = g_coef[b * 2], w1 = g_coef[b * 2 + 1];

    // stage A_e0, A_e1 (coalesced float4 copies)
    {
        float4 a0 = *(const float4*)&lora_A[e0 * IND + tid * 4];
        float4 a1 = *(const float4*)&lora_A[e1 * IND + tid * 4];
        *(float4*)&A2[tid * 4]       = a0;
        *(float4*)&A2[IND + tid * 4] = a1;
    }
    // B rows register-resident (1 float4 per expert per thread)
    float4 B0 = *(const float4*)&lora_B[e0 * OUTD + tid * 4];
    float4 B1 = *(const float4*)&lora_B[e1 * OUTD + tid * 4];
    __syncthreads();

    // ---- phase A: 2 selected dots for this warp's 4 tokens ----
    u64 acc0[TPW], acc1[TPW];
    #pragma unroll
    for (int t = 0; t < TPW; ++t) { acc0[t] = 0ull; acc1[t] = 0ull; }

    const float* xw = x + ((size_t)(b * SSEQ + tokbase + w * TPW)) * IND;

    #pragma unroll
    for (int c = 0; c < 8; ++c) {
        const int koff = c * 128 + lane * 4;
        double2 a0v = *(const double2*)&A2[koff];
        double2 a1v = *(const double2*)&A2[IND + koff];
        u64 a0lo = __double_as_longlong(a0v.x), a0hi = __double_as_longlong(a0v.y);
        u64 a1lo = __double_as_longlong(a1v.x), a1hi = __double_as_longlong(a1v.y);
        #pragma unroll
        for (int t = 0; t < TPW; ++t) {
            double2 xv = *(const double2*)(xw + (size_t)t * IND + koff);
            u64 xlo = __double_as_longlong(xv.x);
            u64 xhi = __double_as_longlong(xv.y);
            fma2(acc0[t], xlo, a0lo);
            fma2(acc0[t], xhi, a0hi);
            fma2(acc1[t], xlo, a1lo);
            fma2(acc1[t], xhi, a1hi);
        }
    }

    #pragma unroll
    for (int t = 0; t < TPW; ++t) {
        float h0 = lo2(acc0[t]) + hi2(acc0[t]);
        float h1 = lo2(acc1[t]) + hi2(acc1[t]);
        #pragma unroll
        for (int off = 16; off; off >>= 1) {
            h0 += __shfl_xor_sync(0xffffffffu, h0, off);
            h1 += __shfl_xor_sync(0xffffffffu, h1, off);
        }
        if (lane == 0) cs[w * TPW + t] = make_float2(w0 * h0, w1 * h1);
    }
    __syncthreads();

    // ---- phase B: R9-k3 store loop (proven shape) ----
    float* ob = out + ((size_t)b * SSEQ + tokbase) * OUTD + tid * 4;
    #pragma unroll 4
    for (int i = 0; i < TOKB; ++i) {
        float2 cc = cs[i];
        float4 v;
        v.x = cc.x * B0.x + cc.y * B1.x;
        v.y = cc.x * B0.y + cc.y * B1.y;
        v.z = cc.x * B0.z + cc.y * B1.z;
        v.w = cc.x * B0.w + cc.y * B1.w;
        stcs4(ob + (size_t)i * OUTD, v);
    }
}

// ------------------------------------------------------------------
extern "C" void kernel_launch(void* const* d_in, const int* in_sizes, int n_in,
                              void* d_out, int out_size) {
    const float* x      = (const float*)d_in[0];
    const float* lora_A = (const float*)d_in[1];
    const float* lora_B = (const float*)d_in[2];
    const float* gate_w = (const float*)d_in[3];
    const float* gate_b = (const float*)d_in[4];
    float* out = (float*)d_out;

    p1_seg<<<BB * (SSEQ / 32), 256>>>(x, gate_w, gate_b);
    p2_out<<<BB * (SSEQ / TOKB), 256>>>(x, lora_A, lora_B, out);
}